// round 16
// baseline (speedup 1.0000x reference)
#include <cuda_runtime.h>
#include <cuda_bf16.h>

#define N_ROWS 65536
#define DIMS   64
#define KCODES 512
#define Q_OFF  1
#define PERP_OFF 4194305
#define ENC_OFF  4194306               // byte offset % 16 == 8
#define FLT_EPS_32 1.1920929e-07f
#define TPB 256
#define GRID_MAIN 128                   // 128 blocks x 2 passes x 256 rows = 65536
#define ROWS_PER_PASS 256
#define CHUNK 256                       // codes per smem chunk
#define NT 32                           // 8-wide n-tiles per chunk
#define WSTRIDE 68                      // padded floats per code row (bank-conflict-free)

// ---- smem byte offsets ----
#define SM_WHI  0                       // 256*68*4 = 69632
#define SM_WLO  69632                   // 69632
#define SM_WSQ  139264                  // 512 f32
#define SM_XSQ  141312                  // 256 f32
#define SM_SBI  142336                  // 256 int
#define SM_ZBUF 143360                  // 512 f32 (stays zero; bulk-copy source, 16B aligned)
#define SM_HIST 145408                  // 512 int
#define SMEM_TOTAL 147456

// ---- scratch (zero at load; tail re-zeros after consumption -> replay-safe) ----
__device__ int    g_counts[KCODES];
__device__ double g_errsum;

__device__ __forceinline__ unsigned f2tf32(float f) {
    unsigned r;
    asm("cvt.rna.tf32.f32 %0, %1;" : "=r"(r) : "f"(f));
    return r;
}

// m16n8k8 tf32 mma: D += A x B (A 16x8 row, B 8x8 col), fp32 accumulate
#define MMA_TF32(c, a0, a1, a2, a3, b0, b1)                                    \
    asm volatile("mma.sync.aligned.m16n8k8.row.col.f32.tf32.tf32.f32 "        \
                 "{%0,%1,%2,%3}, {%4,%5,%6,%7}, {%8,%9}, {%0,%1,%2,%3};"      \
                 : "+f"((c)[0]), "+f"((c)[1]), "+f"((c)[2]), "+f"((c)[3])      \
                 : "r"(a0), "r"(a1), "r"(a2), "r"(a3), "r"(b0), "r"(b1))

__device__ __forceinline__ unsigned smem_u32(const void* p) {
    unsigned a;
    asm("{ .reg .u64 t; cvta.to.shared.u64 t, %1; cvt.u32.u64 %0, t; }" : "=r"(a) : "l"(p));
    return a;
}

__device__ __forceinline__ void bulk_copy(void* gdst, unsigned ssrc, int bytes) {
    asm volatile("cp.async.bulk.global.shared::cta.bulk_group [%0], [%1], %2;"
                 :: "l"(gdst), "r"(ssrc), "r"(bytes) : "memory");
}

// quantized_st row + sum of (q-x)^2, reference rounding. Row base ≡ 1 (mod 4):
// element j is 16B-aligned iff j%4==3. Scalars {0,1,2,63}, float4 at 3..62.
__device__ __forceinline__ float vq_writeout(float* __restrict__ qo,
                                             const float* __restrict__ qr,
                                             const float* __restrict__ xr) {
    float errloc = 0.0f;
#pragma unroll
    for (int jj = 0; jj < 3; jj++) {
        float xv = xr[jj];
        float d  = __fsub_rn(qr[jj], xv);
        qo[jj] = __fadd_rn(xv, d);
        errloc += __fmul_rn(d, d);
    }
    {
        float xv = xr[63];
        float d  = __fsub_rn(qr[63], xv);
        qo[63] = __fadd_rn(xv, d);
        errloc += __fmul_rn(d, d);
    }
#pragma unroll
    for (int i = 0; i < 15; i++) {
        int j = 3 + 4 * i;
        float x0 = xr[j], x1 = xr[j + 1], x2 = xr[j + 2], x3 = xr[j + 3];
        float d0 = __fsub_rn(qr[j    ], x0);
        float d1 = __fsub_rn(qr[j + 1], x1);
        float d2 = __fsub_rn(qr[j + 2], x2);
        float d3 = __fsub_rn(qr[j + 3], x3);
        float4 o;
        o.x = __fadd_rn(x0, d0); o.y = __fadd_rn(x1, d1);
        o.z = __fadd_rn(x2, d2); o.w = __fadd_rn(x3, d3);
        *reinterpret_cast<float4*>(qo + j) = o;
        errloc += __fmul_rn(d0,d0) + __fmul_rn(d1,d1) + __fmul_rn(d2,d2) + __fmul_rn(d3,d3);
    }
    return errloc;
}

// ---------------- main: 3xTF32 mma distance GEMM + argmin + all outputs ----------------
__global__ void __launch_bounds__(TPB, 1) vq_main(const float* __restrict__ x,
                                                  const float* __restrict__ w,
                                                  float* __restrict__ qout,
                                                  float* __restrict__ enc) {
    extern __shared__ char smem[];
    unsigned* whi  = (unsigned*)(smem + SM_WHI);
    unsigned* wlo  = (unsigned*)(smem + SM_WLO);
    float*    swsq = (float*)(smem + SM_WSQ);
    float*    sxsq = (float*)(smem + SM_XSQ);
    int*      sbi  = (int*)(smem + SM_SBI);
    float*    zbuf = (float*)(smem + SM_ZBUF);
    int*      shist= (int*)(smem + SM_HIST);

    int tid  = threadIdx.x;
    int lane = tid & 31, wid = tid >> 5;
    int g = lane >> 2, tig = lane & 3;

    for (int i = tid; i < KCODES; i += TPB) { shist[i] = 0; zbuf[i] = 0.0f; }
    // ||w_k||^2 reference-exact (square rounded, sequential sum)
    for (int c = tid; c < KCODES; c += TPB) {
        const float* wr = w + (size_t)c * DIMS;
        float s = 0.0f;
        for (int d = 0; d < DIMS; d++) s = __fadd_rn(s, __fmul_rn(wr[d], wr[d]));
        swsq[c] = s;
    }
    asm volatile("fence.proxy.async.shared::cta;" ::: "memory");
    __syncthreads();

    unsigned zsrc = smem_u32(zbuf);
    float errloc = 0.0f;

    for (int pass = 0; pass < 2; pass++) {
        int rbase = blockIdx.x * (2 * ROWS_PER_PASS) + pass * ROWS_PER_PASS;
        int r = rbase + tid;

        // enc zero-fill: edges scalar (same thread later writes the 1.0), interior TMA bulk
        float* er = enc + (size_t)r * KCODES;
        er[0] = 0.0f; er[1] = 0.0f; er[510] = 0.0f; er[511] = 0.0f;
        bulk_copy(er + 2, zsrc, 2032);
        asm volatile("cp.async.bulk.commit_group;" ::: "memory");

        // xsq of own row, reference-exact sequential order
        {
            const float4* xp = (const float4*)(x + (size_t)r * DIMS);
            float s = 0.0f;
#pragma unroll
            for (int i = 0; i < 16; i++) {
                float4 v = xp[i];
                s = __fadd_rn(s, __fmul_rn(v.x, v.x));
                s = __fadd_rn(s, __fmul_rn(v.y, v.y));
                s = __fadd_rn(s, __fmul_rn(v.z, v.z));
                s = __fadd_rn(s, __fmul_rn(v.w, v.w));
            }
            sxsq[tid] = s;
        }

        // A fragments (x rows of this warp), tf32 hi/lo in registers
        // m16n8k8: a0=(row g,col tig) a1=(row g+8,col tig) a2=(g,tig+4) a3=(g+8,tig+4)
        unsigned Ahi[2][8][4], Alo[2][8][4];
#pragma unroll
        for (int t = 0; t < 2; t++)
#pragma unroll
            for (int ks = 0; ks < 8; ks++)
#pragma unroll
                for (int e = 0; e < 4; e++) {
                    int row = rbase + wid * 32 + t * 16 + g + (e & 1) * 8;
                    int col = ks * 8 + tig + (e >> 1) * 4;
                    float f = x[(size_t)row * DIMS + col];
                    unsigned hi = f2tf32(f);
                    Ahi[t][ks][e] = hi;
                    Alo[t][ks][e] = f2tf32(__fsub_rn(f, __uint_as_float(hi)));
                }

        float bd[4] = {3.4028235e38f, 3.4028235e38f, 3.4028235e38f, 3.4028235e38f};
        int   bi[4] = {0, 0, 0, 0};

        for (int chunk = 0; chunk < 2; chunk++) {
            __syncthreads();
            // load W chunk -> smem tf32 hi/lo, padded stride 68 (conflict-free frags)
            for (int idx = tid; idx < CHUNK * DIMS; idx += TPB) {
                int n = idx >> 6, c = idx & 63;
                float f = w[(size_t)(chunk * CHUNK + n) * DIMS + c];
                unsigned hi = f2tf32(f);
                whi[n * WSTRIDE + c] = hi;
                wlo[n * WSTRIDE + c] = f2tf32(__fsub_rn(f, __uint_as_float(hi)));
            }
            __syncthreads();

            float xq00 = sxsq[wid * 32 + g];
            float xq01 = sxsq[wid * 32 + g + 8];
            float xq10 = sxsq[wid * 32 + 16 + g];
            float xq11 = sxsq[wid * 32 + 24 + g];

            for (int nt = 0; nt < NT; nt++) {
                float c0[4] = {0.f, 0.f, 0.f, 0.f};
                float c1[4] = {0.f, 0.f, 0.f, 0.f};
                unsigned base = (unsigned)(nt * 8 + g) * WSTRIDE + tig;
                // 3 passes: Ahi*Whi + Ahi*Wlo + Alo*Whi (lo*lo term ~2^-22, dropped)
#pragma unroll
                for (int p = 0; p < 3; p++) {
                    const unsigned* ws = (p == 1) ? wlo : whi;
#pragma unroll
                    for (int ks = 0; ks < 8; ks++) {
                        unsigned b0 = ws[base + ks * 8];
                        unsigned b1 = ws[base + ks * 8 + 4];
                        if (p < 2) {
                            MMA_TF32(c0, Ahi[0][ks][0], Ahi[0][ks][1], Ahi[0][ks][2], Ahi[0][ks][3], b0, b1);
                            MMA_TF32(c1, Ahi[1][ks][0], Ahi[1][ks][1], Ahi[1][ks][2], Ahi[1][ks][3], b0, b1);
                        } else {
                            MMA_TF32(c0, Alo[0][ks][0], Alo[0][ks][1], Alo[0][ks][2], Alo[0][ks][3], b0, b1);
                            MMA_TF32(c1, Alo[1][ks][0], Alo[1][ks][1], Alo[1][ks][2], Alo[1][ks][3], b0, b1);
                        }
                    }
                }
                // epilogue: dist = fl(fl(xsq+wsq) - 2*s), reference rounding; strict < = first-min
                int nc0 = chunk * CHUNK + nt * 8 + 2 * tig;
                float w0 = swsq[nc0], w1 = swsq[nc0 + 1];
                float d;
                d = __fmaf_rn(c0[0], -2.0f, __fadd_rn(xq00, w0)); if (d < bd[0]) { bd[0] = d; bi[0] = nc0;     }
                d = __fmaf_rn(c0[1], -2.0f, __fadd_rn(xq00, w1)); if (d < bd[0]) { bd[0] = d; bi[0] = nc0 + 1; }
                d = __fmaf_rn(c0[2], -2.0f, __fadd_rn(xq01, w0)); if (d < bd[1]) { bd[1] = d; bi[1] = nc0;     }
                d = __fmaf_rn(c0[3], -2.0f, __fadd_rn(xq01, w1)); if (d < bd[1]) { bd[1] = d; bi[1] = nc0 + 1; }
                d = __fmaf_rn(c1[0], -2.0f, __fadd_rn(xq10, w0)); if (d < bd[2]) { bd[2] = d; bi[2] = nc0;     }
                d = __fmaf_rn(c1[1], -2.0f, __fadd_rn(xq10, w1)); if (d < bd[2]) { bd[2] = d; bi[2] = nc0 + 1; }
                d = __fmaf_rn(c1[2], -2.0f, __fadd_rn(xq11, w0)); if (d < bd[3]) { bd[3] = d; bi[3] = nc0;     }
                d = __fmaf_rn(c1[3], -2.0f, __fadd_rn(xq11, w1)); if (d < bd[3]) { bd[3] = d; bi[3] = nc0 + 1; }
            }
        }

        // cross-lane (tig group of 4) lexicographic min -> first-min tie semantics
#pragma unroll
        for (int s = 0; s < 4; s++) {
            float dd = bd[s];
            int   ii = bi[s];
#pragma unroll
            for (int off = 1; off <= 2; off <<= 1) {
                float d2 = __shfl_xor_sync(0xffffffffu, dd, off);
                int   i2 = __shfl_xor_sync(0xffffffffu, ii, off);
                if (d2 < dd || (d2 == dd && i2 < ii)) { dd = d2; ii = i2; }
            }
            if (tig == 0) sbi[wid * 32 + (s >> 1) * 16 + (s & 1) * 8 + g] = ii;
        }
        __syncthreads();

        // writeout: thread <-> local row tid
        int mybi = sbi[tid];
        atomicAdd(&shist[mybi], 1);
        errloc += vq_writeout(qout + (size_t)r * DIMS,
                              w + (size_t)mybi * DIMS,
                              x + (size_t)r * DIMS);
        // own bulk zeros complete, then scatter the 1.0 (same-thread order on edges)
        asm volatile("cp.async.bulk.wait_group 0;" ::: "memory");
        er[mybi] = 1.0f;
    }

    __syncthreads();
    for (int i = tid; i < KCODES; i += TPB)
        if (shist[i]) atomicAdd(&g_counts[i], shist[i]);
#pragma unroll
    for (int o = 16; o > 0; o >>= 1) errloc += __shfl_down_sync(0xffffffffu, errloc, o);
    if (lane == 0) atomicAdd(&g_errsum, (double)errloc);
}

// ---------------- tail: loss + perplexity (+ re-zero accumulators) ----------------
__global__ void __launch_bounds__(512) vq_tail(float* __restrict__ out_loss,
                                               float* __restrict__ out_perp) {
    __shared__ float redv[16];
    int t = threadIdx.x;
    int cnt = g_counts[t];
    g_counts[t] = 0;                       // re-zero for next call (replay-safe)
    float p = (float)cnt * (1.0f / 65536.0f);
    float v = p * __logf(p + FLT_EPS_32);
#pragma unroll
    for (int o = 16; o > 0; o >>= 1) v += __shfl_down_sync(0xffffffffu, v, o);
    if ((t & 31) == 0) redv[t >> 5] = v;
    __syncthreads();
    if (t < 16) {
        float s = redv[t];
#pragma unroll
        for (int o = 8; o > 0; o >>= 1) s += __shfl_down_sync(0xffffu, s, o);
        if (t == 0) {
            *out_perp = __expf(-s);
            double d = g_errsum;
            g_errsum = 0.0;               // re-zero for next call
            float m = (float)(d / 4194304.0);
            *out_loss = __fadd_rn(m, __fmul_rn(0.25f, m));
        }
    }
}

extern "C" void kernel_launch(void* const* d_in, const int* in_sizes, int n_in,
                              void* d_out, int out_size) {
    const float* x = (const float*)d_in[0];
    const float* w = (const float*)d_in[1];
    if (n_in >= 2 && in_sizes[0] == KCODES * DIMS) {
        const float* t = x; x = w; w = t;
    }
    float* out  = (float*)d_out;
    float* qout = out + Q_OFF;
    float* perp = out + PERP_OFF;
    float* enc  = out + ENC_OFF;

    static bool inited = false;
    if (!inited) {   // first call = eager correctness run (not under capture)
        cudaFuncSetAttribute(vq_main, cudaFuncAttributeMaxDynamicSharedMemorySize, SMEM_TOTAL);
        inited = true;
    }

    vq_main<<<GRID_MAIN, TPB, SMEM_TOTAL>>>(x, w, qout, enc);
    vq_tail<<<1, 512>>>(out, perp);
}